// round 6
// baseline (speedup 1.0000x reference)
#include <cuda_runtime.h>
#include <cstdint>

#define N_ROWS 8192
#define DIM    512
#define KSEL   31   // k+1 entries kept per row

// Normalized embeddings scratch (16 MB).
__device__ float g_emb[N_ROWS * DIM];

// ---------------------------------------------------------------------------
// Kernel 1: emb = normalize( relu(features*W1)*W2 ).
// Row-norm reduction replicates XLA-GPU row-reduce for f32[*,512]:
//   256 threads/row, vector size 2: leaf_t = x[2t]^2 + x[2t+1]^2
//   warp shfl_down tree (16,8,4,2,1); 8 warp sums -> smem -> warp0 tree.
// ---------------------------------------------------------------------------
__global__ __launch_bounds__(256) void embed_kernel(
    const float* __restrict__ f,
    const float* __restrict__ w1,
    const float* __restrict__ w2)
{
    const int row  = blockIdx.x;
    const int t    = threadIdx.x;
    const int lane = t & 31;
    const int warp = t >> 5;

    // Each thread owns elements (2t, 2t+1) of the row.
    const float2 v = reinterpret_cast<const float2*>(f + (size_t)row * DIM)[t];
    const float2 a = reinterpret_cast<const float2*>(w1)[t];
    const float2 b = reinterpret_cast<const float2*>(w2)[t];

    float h0 = __fmul_rn(fmaxf(__fmul_rn(v.x, a.x), 0.0f), b.x);
    float h1 = __fmul_rn(fmaxf(__fmul_rn(v.y, a.y), 0.0f), b.y);

    // leaf = (0 + h0*h0) + h1*h1  (0+x exact)
    float acc = __fadd_rn(__fmul_rn(h0, h0), __fmul_rn(h1, h1));

    // Warp tree, shfl_down offsets 16,8,4,2,1.
    #pragma unroll
    for (int off = 16; off > 0; off >>= 1)
        acc = __fadd_rn(acc, __shfl_down_sync(0xFFFFFFFFu, acc, off));

    __shared__ float s_w[8];
    __shared__ float s_nrm;
    if (lane == 0) s_w[warp] = acc;
    __syncthreads();

    if (warp == 0) {
        float x = (lane < 8) ? s_w[lane] : 0.0f;
        #pragma unroll
        for (int off = 16; off > 0; off >>= 1)
            x = __fadd_rn(x, __shfl_down_sync(0xFFFFFFFFu, x, off));
        if (lane == 0)
            s_nrm = fmaxf(__fsqrt_rn(x), 1e-12f);
    }
    __syncthreads();

    const float nrm = s_nrm;
    float2 o;
    o.x = __fdiv_rn(h0, nrm);
    o.y = __fdiv_rn(h1, nrm);
    reinterpret_cast<float2*>(g_emb + (size_t)row * DIM)[t] = o;
}

// ---------------------------------------------------------------------------
// Kernel 2: C = E * E^T, plain fp32, SINGLE accumulator per output, k strictly
// ascending with fma.rn — matches cuBLAS SGEMM / Eigen accumulation order.
// 128x128x32 tiles, 256 threads, 8x8 micro-tile.
// Symmetric: compute upper-triangular blocks, mirror-write transpose.
// ---------------------------------------------------------------------------
#define BM 128
#define BN 128
#define BK 32
#define SMS 132   // padded smem row stride (floats)

__global__ __launch_bounds__(256) void gemm_sym_kernel(
    const float* __restrict__ E,
    float* __restrict__ C)
{
    const int bx = blockIdx.x;   // column block
    const int by = blockIdx.y;   // row block
    if (by > bx) return;         // upper triangle only

    __shared__ float As[BK][SMS];
    __shared__ float Bs[BK][SMS];

    const int tid = threadIdx.x;
    const int tx  = tid & 15;
    const int ty  = tid >> 4;

    const int rowBase = by * BM;
    const int colBase = bx * BN;

    float acc[8][8];
    #pragma unroll
    for (int i = 0; i < 8; i++)
        #pragma unroll
        for (int j = 0; j < 8; j++)
            acc[i][j] = 0.0f;

    for (int k0 = 0; k0 < DIM; k0 += BK) {
        #pragma unroll
        for (int l = 0; l < 4; l++) {
            const int a  = tid + l * 256;
            const int r  = a >> 3;
            const int kk = (a & 7) * 4;
            float4 va = *reinterpret_cast<const float4*>(
                &E[(size_t)(rowBase + r) * DIM + k0 + kk]);
            As[kk + 0][r] = va.x; As[kk + 1][r] = va.y;
            As[kk + 2][r] = va.z; As[kk + 3][r] = va.w;
            float4 vb = *reinterpret_cast<const float4*>(
                &E[(size_t)(colBase + r) * DIM + k0 + kk]);
            Bs[kk + 0][r] = vb.x; Bs[kk + 1][r] = vb.y;
            Bs[kk + 2][r] = vb.z; Bs[kk + 3][r] = vb.w;
        }
        __syncthreads();

        #pragma unroll
        for (int k = 0; k < BK; k++) {   // k strictly ascending
            float ar[8], br[8];
            *reinterpret_cast<float4*>(&ar[0]) =
                *reinterpret_cast<const float4*>(&As[k][ty * 4]);
            *reinterpret_cast<float4*>(&ar[4]) =
                *reinterpret_cast<const float4*>(&As[k][64 + ty * 4]);
            *reinterpret_cast<float4*>(&br[0]) =
                *reinterpret_cast<const float4*>(&Bs[k][tx * 4]);
            *reinterpret_cast<float4*>(&br[4]) =
                *reinterpret_cast<const float4*>(&Bs[k][64 + tx * 4]);
            #pragma unroll
            for (int i = 0; i < 8; i++)
                #pragma unroll
                for (int j = 0; j < 8; j++)
                    acc[i][j] = __fmaf_rn(ar[i], br[j], acc[i][j]);
        }
        __syncthreads();
    }

    // Normal (upper) block write.
    #pragma unroll
    for (int qi = 0; qi < 2; qi++) {
        #pragma unroll
        for (int i = 0; i < 4; i++) {
            const int li = qi * 4 + i;
            const int gr = rowBase + qi * 64 + ty * 4 + i;
            float4 w0 = make_float4(acc[li][0], acc[li][1], acc[li][2], acc[li][3]);
            float4 w1 = make_float4(acc[li][4], acc[li][5], acc[li][6], acc[li][7]);
            *reinterpret_cast<float4*>(&C[(size_t)gr * N_ROWS + colBase + tx * 4])      = w0;
            *reinterpret_cast<float4*>(&C[(size_t)gr * N_ROWS + colBase + 64 + tx * 4]) = w1;
        }
    }

    // Mirror (lower) block.
    if (bx != by) {
        #pragma unroll
        for (int qj = 0; qj < 2; qj++) {
            #pragma unroll
            for (int j = 0; j < 4; j++) {
                const int lj = qj * 4 + j;
                const int gc = colBase + qj * 64 + tx * 4 + j;
                float4 w0 = make_float4(acc[0][lj], acc[1][lj], acc[2][lj], acc[3][lj]);
                float4 w1 = make_float4(acc[4][lj], acc[5][lj], acc[6][lj], acc[7][lj]);
                *reinterpret_cast<float4*>(&C[(size_t)gc * N_ROWS + rowBase + ty * 4])      = w0;
                *reinterpret_cast<float4*>(&C[(size_t)gc * N_ROWS + rowBase + 64 + ty * 4]) = w1;
            }
        }
    }
}

// ---------------------------------------------------------------------------
// Kernel 3: per-row top-KSEL threshold via radix select on fp32 grid +
// lowest-index tie-break (jax.lax.top_k semantics), then mask + relu.
// ---------------------------------------------------------------------------
__device__ __forceinline__ unsigned f2key(float v) {
    unsigned u = __float_as_uint(v);
    return (u & 0x80000000u) ? ~u : (u | 0x80000000u);
}
__device__ __forceinline__ float key2f(unsigned k) {
    unsigned u = (k & 0x80000000u) ? (k & 0x7FFFFFFFu) : ~k;
    return __uint_as_float(u);
}

#define MAX_TIES 64

__global__ __launch_bounds__(256) void topk_mask_kernel(float* __restrict__ C)
{
    __shared__ unsigned keys[N_ROWS];
    __shared__ unsigned hist[256];
    __shared__ unsigned s_prefix;
    __shared__ int      s_rem;
    __shared__ int      eq_idx[MAX_TIES];
    __shared__ int      eq_n;

    const int row = blockIdx.x;
    const int tid = threadIdx.x;
    float* __restrict__ rowp = C + (size_t)row * N_ROWS;

    for (int i = tid; i < N_ROWS; i += 256)
        keys[i] = f2key(rowp[i]);
    if (tid == 0) eq_n = 0;
    __syncthreads();

    unsigned prefix = 0;
    int remaining = KSEL;

    #pragma unroll
    for (int shift = 24; shift >= 0; shift -= 8) {
        hist[tid] = 0;
        __syncthreads();

        const unsigned himask = (shift == 24) ? 0u : (0xFFFFFFFFu << (shift + 8));
        for (int i = tid; i < N_ROWS; i += 256) {
            const unsigned k = keys[i];
            if ((k & himask) == prefix)
                atomicAdd(&hist[(k >> shift) & 255u], 1u);
        }
        __syncthreads();

        if (tid == 0) {
            int cum = 0, b = 255;
            for (; b >= 0; b--) {
                cum += (int)hist[b];
                if (cum >= remaining) break;
            }
            if (b < 0) b = 0;
            s_prefix = prefix | ((unsigned)b << shift);
            s_rem    = remaining - (cum - (int)hist[b]);
        }
        __syncthreads();
        prefix    = s_prefix;
        remaining = s_rem;
        __syncthreads();
    }

    for (int i = tid; i < N_ROWS; i += 256) {
        if (keys[i] == prefix) {
            int p = atomicAdd(&eq_n, 1);
            if (p < MAX_TIES) eq_idx[p] = i;
        }
    }
    __syncthreads();
    const int m = eq_n;

    for (int i = tid; i < N_ROWS; i += 256) {
        const unsigned k = keys[i];
        float out = 0.0f;
        if (k > prefix) {
            out = fmaxf(key2f(k), 0.0f);
        } else if (k == prefix) {
            bool keep;
            if (m <= remaining || m > MAX_TIES) {
                keep = true;
            } else {
                int r = 0;
                for (int j = 0; j < m; j++) r += (eq_idx[j] < i);
                keep = (r < remaining);
            }
            if (keep) out = fmaxf(key2f(k), 0.0f);
        }
        rowp[i] = out;
    }
}

// ---------------------------------------------------------------------------
extern "C" void kernel_launch(void* const* d_in, const int* in_sizes, int n_in,
                              void* d_out, int out_size)
{
    const float* features = (const float*)d_in[0];  // [8192, 512]
    const float* W1       = (const float*)d_in[1];  // [512]
    const float* W2       = (const float*)d_in[2];  // [512]
    float* out            = (float*)d_out;          // [8192, 8192]

    float* emb = nullptr;
    cudaGetSymbolAddress((void**)&emb, g_emb);

    embed_kernel<<<N_ROWS, 256>>>(features, W1, W2);
    gemm_sym_kernel<<<dim3(N_ROWS / BN, N_ROWS / BM), 256>>>(emb, out);
    topk_mask_kernel<<<N_ROWS, 256>>>(out);
}

// round 7
// speedup vs baseline: 1.0179x; 1.0179x over previous
#include <cuda_runtime.h>
#include <cstdint>

#define N_ROWS 8192
#define DIM    512
#define KSEL   31   // k+1 entries kept per row

// Normalized embeddings scratch (16 MB).
__device__ float g_emb[N_ROWS * DIM];

// ---------------------------------------------------------------------------
// Kernel 1: emb = normalize( relu(features*W1)*W2 ).  (DO NOT TOUCH — bit-
// matches reference: vec2 leaf, warp shfl_down tree, 8 warp sums, warp0 tree.)
// ---------------------------------------------------------------------------
__global__ __launch_bounds__(256) void embed_kernel(
    const float* __restrict__ f,
    const float* __restrict__ w1,
    const float* __restrict__ w2)
{
    const int row  = blockIdx.x;
    const int t    = threadIdx.x;
    const int lane = t & 31;
    const int warp = t >> 5;

    const float2 v = reinterpret_cast<const float2*>(f + (size_t)row * DIM)[t];
    const float2 a = reinterpret_cast<const float2*>(w1)[t];
    const float2 b = reinterpret_cast<const float2*>(w2)[t];

    float h0 = __fmul_rn(fmaxf(__fmul_rn(v.x, a.x), 0.0f), b.x);
    float h1 = __fmul_rn(fmaxf(__fmul_rn(v.y, a.y), 0.0f), b.y);

    float acc = __fadd_rn(__fmul_rn(h0, h0), __fmul_rn(h1, h1));

    #pragma unroll
    for (int off = 16; off > 0; off >>= 1)
        acc = __fadd_rn(acc, __shfl_down_sync(0xFFFFFFFFu, acc, off));

    __shared__ float s_w[8];
    __shared__ float s_nrm;
    if (lane == 0) s_w[warp] = acc;
    __syncthreads();

    if (warp == 0) {
        float x = (lane < 8) ? s_w[lane] : 0.0f;
        #pragma unroll
        for (int off = 16; off > 0; off >>= 1)
            x = __fadd_rn(x, __shfl_down_sync(0xFFFFFFFFu, x, off));
        if (lane == 0)
            s_nrm = fmaxf(__fsqrt_rn(x), 1e-12f);
    }
    __syncthreads();

    const float nrm = s_nrm;
    float2 o;
    o.x = __fdiv_rn(h0, nrm);
    o.y = __fdiv_rn(h1, nrm);
    reinterpret_cast<float2*>(g_emb + (size_t)row * DIM)[t] = o;
}

// ---------------------------------------------------------------------------
// Kernel 2: C = E * E^T. Packed fp32 FFMA2 (fma.rn.f32x2): 2 IEEE fp32 FMAs
// per instruction, per-lane rounding identical to __fmaf_rn, k strictly
// ascending with a single accumulator per output -> bit-identical to R6.
// 128x128x32 tiles, 256 threads, 8x8 micro-tile (accumulators packed j-pairs).
// Grid linearized over the 2080 upper-triangle blocks; mirror-write transpose.
// ---------------------------------------------------------------------------
#define BM 128
#define BN 128
#define BK 32
#define SMS 132   // padded smem row stride (floats)
#define NB  (N_ROWS / BM)         // 64 blocks per dim
#define NTRI (NB * (NB + 1) / 2)  // 2080 upper-triangle blocks

#define FMA2(acc, a, b) \
    asm("fma.rn.f32x2 %0, %1, %2, %0;" : "+d"(acc) : "d"(a), "d"(b))
#define DUP2(dst, s) \
    asm("mov.b64 %0, {%1, %1};" : "=d"(dst) : "f"(s))
#define UNPK2(lo, hi, p) \
    asm("mov.b64 {%0, %1}, %2;" : "=f"(lo), "=f"(hi) : "d"(p))

__global__ __launch_bounds__(256) void gemm_sym_kernel(
    const float* __restrict__ E,
    float* __restrict__ C)
{
    // Decode linear triangle index -> (by, bx), by <= bx.
    const int t5 = blockIdx.x;
    int by = (int)((2.0 * NB + 1.0 - sqrt((2.0 * NB + 1.0) * (2.0 * NB + 1.0)
                                          - 8.0 * (double)t5)) * 0.5);
    // offset(by) = by*NB - by*(by-1)/2
    while (by > 0    && (by * NB - (by * (by - 1)) / 2) > t5) by--;
    while (by < NB-1 && ((by + 1) * NB - ((by + 1) * by) / 2) <= t5) by++;
    const int bx = by + (t5 - (by * NB - (by * (by - 1)) / 2));

    __shared__ float As[BK][SMS];
    __shared__ float Bs[BK][SMS];

    const int tid = threadIdx.x;
    const int tx  = tid & 15;
    const int ty  = tid >> 4;

    const int rowBase = by * BM;
    const int colBase = bx * BN;

    // Packed accumulators: accp[i][q] holds (acc[i][2q], acc[i][2q+1]).
    double accp[8][4];
    #pragma unroll
    for (int i = 0; i < 8; i++)
        #pragma unroll
        for (int q = 0; q < 4; q++)
            accp[i][q] = 0.0;   // bit pattern = (+0.0f, +0.0f)

    for (int k0 = 0; k0 < DIM; k0 += BK) {
        #pragma unroll
        for (int l = 0; l < 4; l++) {
            const int a  = tid + l * 256;
            const int r  = a >> 3;
            const int kk = (a & 7) * 4;
            float4 va = *reinterpret_cast<const float4*>(
                &E[(size_t)(rowBase + r) * DIM + k0 + kk]);
            As[kk + 0][r] = va.x; As[kk + 1][r] = va.y;
            As[kk + 2][r] = va.z; As[kk + 3][r] = va.w;
            float4 vb = *reinterpret_cast<const float4*>(
                &E[(size_t)(colBase + r) * DIM + k0 + kk]);
            Bs[kk + 0][r] = vb.x; Bs[kk + 1][r] = vb.y;
            Bs[kk + 2][r] = vb.z; Bs[kk + 3][r] = vb.w;
        }
        __syncthreads();

        #pragma unroll
        for (int k = 0; k < BK; k++) {   // k strictly ascending
            float ar[8];
            *reinterpret_cast<float4*>(&ar[0]) =
                *reinterpret_cast<const float4*>(&As[k][ty * 4]);
            *reinterpret_cast<float4*>(&ar[4]) =
                *reinterpret_cast<const float4*>(&As[k][64 + ty * 4]);
            // B fragment as pre-packed f32x2 pairs (bit reinterpret only).
            double2 bq0 = *reinterpret_cast<const double2*>(&Bs[k][tx * 4]);
            double2 bq1 = *reinterpret_cast<const double2*>(&Bs[k][64 + tx * 4]);

            double ad[8];
            #pragma unroll
            for (int i = 0; i < 8; i++) DUP2(ad[i], ar[i]);

            #pragma unroll
            for (int i = 0; i < 8; i++) {
                FMA2(accp[i][0], ad[i], bq0.x);
                FMA2(accp[i][1], ad[i], bq0.y);
                FMA2(accp[i][2], ad[i], bq1.x);
                FMA2(accp[i][3], ad[i], bq1.y);
            }
        }
        __syncthreads();
    }

    // Unpack to scalars.
    float acc[8][8];
    #pragma unroll
    for (int i = 0; i < 8; i++)
        #pragma unroll
        for (int q = 0; q < 4; q++)
            UNPK2(acc[i][2 * q], acc[i][2 * q + 1], accp[i][q]);

    // Normal (upper) block write.
    #pragma unroll
    for (int qi = 0; qi < 2; qi++) {
        #pragma unroll
        for (int i = 0; i < 4; i++) {
            const int li = qi * 4 + i;
            const int gr = rowBase + qi * 64 + ty * 4 + i;
            float4 w0 = make_float4(acc[li][0], acc[li][1], acc[li][2], acc[li][3]);
            float4 w1 = make_float4(acc[li][4], acc[li][5], acc[li][6], acc[li][7]);
            *reinterpret_cast<float4*>(&C[(size_t)gr * N_ROWS + colBase + tx * 4])      = w0;
            *reinterpret_cast<float4*>(&C[(size_t)gr * N_ROWS + colBase + 64 + tx * 4]) = w1;
        }
    }

    // Mirror (lower) block.
    if (bx != by) {
        #pragma unroll
        for (int qj = 0; qj < 2; qj++) {
            #pragma unroll
            for (int j = 0; j < 4; j++) {
                const int lj = qj * 4 + j;
                const int gc = colBase + qj * 64 + tx * 4 + j;
                float4 w0 = make_float4(acc[0][lj], acc[1][lj], acc[2][lj], acc[3][lj]);
                float4 w1 = make_float4(acc[4][lj], acc[5][lj], acc[6][lj], acc[7][lj]);
                *reinterpret_cast<float4*>(&C[(size_t)gc * N_ROWS + rowBase + ty * 4])      = w0;
                *reinterpret_cast<float4*>(&C[(size_t)gc * N_ROWS + rowBase + 64 + ty * 4]) = w1;
            }
        }
    }
}

// ---------------------------------------------------------------------------
// Kernel 3: per-row top-KSEL threshold via radix select on fp32 grid +
// lowest-index tie-break (jax.lax.top_k semantics), then mask + relu.
// ---------------------------------------------------------------------------
__device__ __forceinline__ unsigned f2key(float v) {
    unsigned u = __float_as_uint(v);
    return (u & 0x80000000u) ? ~u : (u | 0x80000000u);
}
__device__ __forceinline__ float key2f(unsigned k) {
    unsigned u = (k & 0x80000000u) ? (k & 0x7FFFFFFFu) : ~k;
    return __uint_as_float(u);
}

#define MAX_TIES 64

__global__ __launch_bounds__(256) void topk_mask_kernel(float* __restrict__ C)
{
    __shared__ unsigned keys[N_ROWS];
    __shared__ unsigned hist[256];
    __shared__ unsigned s_prefix;
    __shared__ int      s_rem;
    __shared__ int      eq_idx[MAX_TIES];
    __shared__ int      eq_n;

    const int row = blockIdx.x;
    const int tid = threadIdx.x;
    float* __restrict__ rowp = C + (size_t)row * N_ROWS;

    for (int i = tid; i < N_ROWS; i += 256)
        keys[i] = f2key(rowp[i]);
    if (tid == 0) eq_n = 0;
    __syncthreads();

    unsigned prefix = 0;
    int remaining = KSEL;

    #pragma unroll
    for (int shift = 24; shift >= 0; shift -= 8) {
        hist[tid] = 0;
        __syncthreads();

        const unsigned himask = (shift == 24) ? 0u : (0xFFFFFFFFu << (shift + 8));
        for (int i = tid; i < N_ROWS; i += 256) {
            const unsigned k = keys[i];
            if ((k & himask) == prefix)
                atomicAdd(&hist[(k >> shift) & 255u], 1u);
        }
        __syncthreads();

        if (tid == 0) {
            int cum = 0, b = 255;
            for (; b >= 0; b--) {
                cum += (int)hist[b];
                if (cum >= remaining) break;
            }
            if (b < 0) b = 0;
            s_prefix = prefix | ((unsigned)b << shift);
            s_rem    = remaining - (cum - (int)hist[b]);
        }
        __syncthreads();
        prefix    = s_prefix;
        remaining = s_rem;
        __syncthreads();
    }

    for (int i = tid; i < N_ROWS; i += 256) {
        if (keys[i] == prefix) {
            int p = atomicAdd(&eq_n, 1);
            if (p < MAX_TIES) eq_idx[p] = i;
        }
    }
    __syncthreads();
    const int m = eq_n;

    for (int i = tid; i < N_ROWS; i += 256) {
        const unsigned k = keys[i];
        float out = 0.0f;
        if (k > prefix) {
            out = fmaxf(key2f(k), 0.0f);
        } else if (k == prefix) {
            bool keep;
            if (m <= remaining || m > MAX_TIES) {
                keep = true;
            } else {
                int r = 0;
                for (int j = 0; j < m; j++) r += (eq_idx[j] < i);
                keep = (r < remaining);
            }
            if (keep) out = fmaxf(key2f(k), 0.0f);
        }
        rowp[i] = out;
    }
}

// ---------------------------------------------------------------------------
extern "C" void kernel_launch(void* const* d_in, const int* in_sizes, int n_in,
                              void* d_out, int out_size)
{
    const float* features = (const float*)d_in[0];  // [8192, 512]
    const float* W1       = (const float*)d_in[1];  // [512]
    const float* W2       = (const float*)d_in[2];  // [512]
    float* out            = (float*)d_out;          // [8192, 8192]

    float* emb = nullptr;
    cudaGetSymbolAddress((void**)&emb, g_emb);

    embed_kernel<<<N_ROWS, 256>>>(features, W1, W2);
    gemm_sym_kernel<<<NTRI, 256>>>(emb, out);
    topk_mask_kernel<<<N_ROWS, 256>>>(out);
}